// round 5
// baseline (speedup 1.0000x reference)
#include <cuda_runtime.h>
#include <math.h>

#define BB 8
#define CH 64
#define HH 256
#define WW 256
#define HW 65536

typedef unsigned long long u64;

__device__ __forceinline__ u64 pk2(float lo, float hi){ u64 r; asm("mov.b64 %0,{%1,%2};" : "=l"(r) : "f"(lo), "f"(hi)); return r; }
__device__ __forceinline__ u64 splat2(float v){ u64 r; asm("mov.b64 %0,{%1,%1};" : "=l"(r) : "f"(v)); return r; }
__device__ __forceinline__ float2 upk2(u64 a){ float2 f; asm("mov.b64 {%0,%1},%2;" : "=f"(f.x), "=f"(f.y) : "l"(a)); return f; }
__device__ __forceinline__ u64 f2fma(u64 a, u64 b, u64 c){ u64 d; asm("fma.rn.f32x2 %0,%1,%2,%3;" : "=l"(d) : "l"(a), "l"(b), "l"(c)); return d; }
__device__ __forceinline__ u64 f2add(u64 a, u64 b){ u64 d; asm("add.rn.f32x2 %0,%1,%2;" : "=l"(d) : "l"(a), "l"(b)); return d; }

// fast tanh: 1 - 2/(1+2^(x*2*log2 e)). MUFU EX2 + MUFU RCP, ~1e-6 abs err,
// exact saturation at +/-inf (inf->1, 0->-1).
__device__ __forceinline__ float fast_tanh(float x){
    float e, r;
    asm("ex2.approx.f32 %0, %1;" : "=f"(e) : "f"(x * 2.8853900817779268f));
    asm("rcp.approx.f32 %0, %1;" : "=f"(r) : "f"(e + 1.0f));
    return fmaf(-2.0f, r, 1.0f);
}

// Scratch (device globals: no allocation allowed)
__device__ float g_h0[BB*CH*HW];      // 2*tanh(enc) field (134 MB)
__device__ float g_v [BB*CH*64];      // projected modes [b][c][kxi*8+ky*2+{re,im}]
__device__ float g_gA[BB*CH*64];      // final mode state after 6 iterations
__device__ float g_Z [BB*HH*CH*8];    // per-row recon coeffs [b][h][c][f0,fr1,fi1,fr2,fi2,fr3,fi3,pad]
__device__ float g_wre[32*4096];      // repacked mix weights [slice][i*64+o]
__device__ float g_wim[32*4096];

// ---------------------------------------------------------------------------
// K0: repack spectral weights. slice s = kxi*4+ky; entry i*64+o.
// ---------------------------------------------------------------------------
__global__ void k_repack(const float* __restrict__ w1r, const float* __restrict__ w1i,
                         const float* __restrict__ w2r, const float* __restrict__ w2i)
{
    int s = blockIdx.x;
    int kxi = s >> 2, ky = s & 3;
    const float* srcr = (kxi < 4) ? w1r : w2r;
    const float* srci = (kxi < 4) ? w1i : w2i;
    int kk = (kxi & 3) * 4 + ky;
    for (int idx = threadIdx.x; idx < 4096; idx += blockDim.x) {
        g_wre[s*4096 + idx] = srcr[idx*16 + kk];
        g_wim[s*4096 + idx] = srci[idx*16 + kk];
    }
}

// ---------------------------------------------------------------------------
// K1: encoder  h0 = 2*tanh(enc_w @ x + enc_b)   (skip 2x folded here)
// ---------------------------------------------------------------------------
__global__ void k_encode(const float* __restrict__ x,
                         const float* __restrict__ ew,
                         const float* __restrict__ eb)
{
    __shared__ float sw[192];
    __shared__ float sb[64];
    int t = threadIdx.x;
    if (t < 192) sw[t] = ew[t];
    if (t < 64)  sb[t] = eb[t];
    __syncthreads();

    int w = t, h = blockIdx.x, b = blockIdx.y;
    const float* xp = x + ((b*3)*HH + h)*WW + w;
    float x0 = xp[0], x1 = xp[HW], x2 = xp[2*HW];
    float* hp = g_h0 + (b*CH*HH + h)*WW + w;
    #pragma unroll 8
    for (int c = 0; c < CH; c++) {
        float v = fmaf(sw[3*c], x0, fmaf(sw[3*c+1], x1, fmaf(sw[3*c+2], x2, sb[c])));
        hp[c*HW] = 2.f * fast_tanh(v);
    }
}

// ---------------------------------------------------------------------------
// K2: projection v = P h0 (scaled 2x since h0 is doubled; folded out in K4).
// ---------------------------------------------------------------------------
__global__ void k_project()
{
    __shared__ float ph[256][8];
    __shared__ float red[8][64];
    int w = threadIdx.x, c = blockIdx.x, b = blockIdx.y;

    float a = 6.28318530717958647692f * (1.0f/256.0f) * (float)w;
    float c1, s1; sincosf(a, &s1, &c1);
    float c2 = c1*c1 - s1*s1,  s2 = 2.f*s1*c1;
    float c3 = c2*c1 - s2*s1,  s3 = s2*c1 + c2*s1;
    float c4 = c2*c2 - s2*s2,  s4 = 2.f*s2*c2;
    ph[w][0]=c1; ph[w][1]=s1; ph[w][2]=c2; ph[w][3]=s2;
    ph[w][4]=c3; ph[w][5]=s3; ph[w][6]=c4; ph[w][7]=s4;
    __syncthreads();

    const float* hp = g_h0 + (b*CH + c)*HW + w;
    float a0=0.f, ar1=0.f, b1=0.f, ar2=0.f, b2=0.f, ar3=0.f, b3=0.f, ar4=0.f, b4=0.f;
    #pragma unroll 4
    for (int hh = 0; hh < 256; hh++) {
        float v = hp[hh*256];
        float4 p0 = *(const float4*)&ph[hh][0];
        float4 p1 = *(const float4*)&ph[hh][4];
        a0 += v;
        ar1 = fmaf(v, p0.x, ar1);  b1 = fmaf(v, p0.y, b1);
        ar2 = fmaf(v, p0.z, ar2);  b2 = fmaf(v, p0.w, b2);
        ar3 = fmaf(v, p1.x, ar3);  b3 = fmaf(v, p1.y, b3);
        ar4 = fmaf(v, p1.z, ar4);  b4 = fmaf(v, p1.w, b4);
    }

    float crr[8] = {a0,  ar1, ar2, ar3, ar4, ar3, ar2, ar1};
    float cii[8] = {0.f, -b1, -b2, -b3,  b4,  b3,  b2,  b1};
    float cyk[4] = {1.f, c1, c2, c3};
    float syk[4] = {0.f, s1, s2, s3};

    int lane = w & 31, wid = w >> 5;
    #pragma unroll
    for (int kxi = 0; kxi < 8; kxi++) {
        #pragma unroll
        for (int ky = 0; ky < 4; ky++) {
            float re = crr[kxi]*cyk[ky] + cii[kxi]*syk[ky];
            float im = cii[kxi]*cyk[ky] - crr[kxi]*syk[ky];
            #pragma unroll
            for (int o = 16; o > 0; o >>= 1) {
                re += __shfl_xor_sync(0xffffffffu, re, o);
                im += __shfl_xor_sync(0xffffffffu, im, o);
            }
            if (lane == 0) {
                red[wid][(kxi*4+ky)*2    ] = re;
                red[wid][(kxi*4+ky)*2 + 1] = im;
            }
        }
    }
    __syncthreads();
    if (w < 64) {
        float s = 0.f;
        #pragma unroll
        for (int q = 0; q < 8; q++) s += red[q][w];
        g_v[(b*CH + c)*64 + w] = s;
    }
}

// ---------------------------------------------------------------------------
// K3: ALL 6 mode-space iterations fused.
// ---------------------------------------------------------------------------
__global__ void __launch_bounds__(128) k_mix6()
{
    extern __shared__ float smw[];
    float* swr = smw;          // [2][4096]
    float* swi = smw + 8192;
    __shared__ float vr[2][64], vi[2][64], gr[2][64], gi[2][64], fr[2][64], fi[2][64];

    int g = blockIdx.x, b = blockIdx.y, tid = threadIdx.x;
    int s0, s1 = -1, tmode;
    if (g < 24)      { int kxi=g/3, ky=g%3+1; s0=kxi*4+ky; tmode=0; }
    else if (g==24)  { s0=0;           tmode=1; }
    else if (g==25)  { s0=16;          tmode=2; }
    else if (g==26)  { s0=4;  s1=28;   tmode=3; }
    else if (g==27)  { s0=8;  s1=24;   tmode=3; }
    else             { s0=12; s1=20;   tmode=3; }
    int nsl = (s1 >= 0) ? 2 : 1;

    for (int q = 0; q < nsl; q++) {
        int s = q ? s1 : s0;
        for (int idx = tid; idx < 4096; idx += 128) {
            swr[q*4096 + idx] = g_wre[s*4096 + idx];
            swi[q*4096 + idx] = g_wim[s*4096 + idx];
        }
    }
    int sl = tid >> 6, o = tid & 63;
    if (sl < nsl) {
        int s = sl ? s1 : s0;
        int base = (b*64 + o)*64 + s*2;
        vr[sl][o] = g_v[base]; vi[sl][o] = g_v[base+1];
    }
    __syncthreads();

    for (int it = 0; it < 6; it++) {
        if (sl < nsl) {
            float tr = 0.f, ti = 0.f;
            if (it > 0) {
                float grv = gr[sl][o], giv = gi[sl][o];
                if      (tmode == 0) { tr = grv;       ti = giv; }
                else if (tmode == 1) { tr = grv;       ti = 0.f; }
                else if (tmode == 2) { tr = 0.5f*grv;  ti = 0.5f*giv; }
                else { tr = 0.5f*(grv + gr[1-sl][o]);  ti = 0.5f*(giv - gi[1-sl][o]); }
            }
            fr[sl][o] = vr[sl][o] + tr;
            fi[sl][o] = vi[sl][o] + ti;
        }
        __syncthreads();
        float accr = 0.f, acci = 0.f;
        if (sl < nsl) {
            const float* wrp = swr + sl*4096;
            const float* wip = swi + sl*4096;
            #pragma unroll 8
            for (int i = 0; i < 64; i++) {
                float w_r = wrp[i*64 + o], w_i = wip[i*64 + o];
                float f_r = fr[sl][i],     f_i = fi[sl][i];
                accr = fmaf(f_r, w_r, accr); accr = fmaf(-f_i, w_i, accr);
                acci = fmaf(f_r, w_i, acci); acci = fmaf( f_i, w_r, acci);
            }
        }
        __syncthreads();
        if (sl < nsl) {
            float g0r = it ? gr[sl][o] : 0.f;
            float g0i = it ? gi[sl][o] : 0.f;
            gr[sl][o] = g0r + accr;
            gi[sl][o] = g0i + acci;
        }
        __syncthreads();
    }

    if (sl < nsl) {
        int s = sl ? s1 : s0;
        int base = (b*64 + o)*64 + s*2;
        g_gA[base]   = gr[sl][o];
        g_gA[base+1] = gi[sl][o];
    }
}

// ---------------------------------------------------------------------------
// K4: per-row reconstruction coefficients (0.5 folded for doubled h0).
// ---------------------------------------------------------------------------
__global__ void k_ztable()
{
    __shared__ float gm[64];
    int h = threadIdx.x, c = blockIdx.x, b = blockIdx.y;
    if (h < 64) gm[h] = g_gA[(b*CH + c)*64 + h];
    __syncthreads();

    float a = 6.28318530717958647692f * (1.0f/256.0f) * (float)h;
    float c1, s1; sincosf(a, &s1, &c1);
    float c2 = c1*c1 - s1*s1,  s2 = 2.f*s1*c1;
    float c3 = c2*c1 - s2*s1,  s3 = s2*c1 + c2*s1;
    float c4 = c2*c2 - s2*s2,  s4 = 2.f*s2*c2;
    float pc[8] = {1.f, c1, c2, c3,  c4,  c3,  c2,  c1};
    float ps[8] = {0.f, s1, s2, s3, -s4, -s3, -s2, -s1};

    float outv[8];
    #pragma unroll
    for (int ky = 0; ky < 4; ky++) {
        float zr = 0.f, zi = 0.f;
        #pragma unroll
        for (int kxi = 0; kxi < 8; kxi++) {
            float grv = gm[kxi*8 + ky*2], giv = gm[kxi*8 + ky*2 + 1];
            zr += grv*pc[kxi] - giv*ps[kxi];
            zi += grv*ps[kxi] + giv*pc[kxi];
        }
        if (ky == 0) outv[0] = zr * (1.f/131072.f);
        else { outv[ky*2-1] = zr * (1.f/65536.f);
               outv[ky*2  ] = zi * (1.f/65536.f); }
    }
    outv[7] = 0.f;

    float* zp = g_Z + ((b*HH + h)*CH + c)*8;
    #pragma unroll
    for (int j = 0; j < 8; j++) zp[j] = outv[j];
}

// ---------------------------------------------------------------------------
// K5: fused epilogue, f32x2 over output-channel pairs, TWO ROWS per thread.
// Rows h,h+1 share w-phases and dec1 weights: Z packed as row-pairs so the
// recon is 8 f2fma for two pixels; weight LDS amortized 2x.
// block = 256 threads (one w each), grid = (128, 8).
// ---------------------------------------------------------------------------
__global__ void __launch_bounds__(256) k_final(
    const float* __restrict__ d1w, const float* __restrict__ d1b,
    const float* __restrict__ d2w, const float* __restrict__ d2b,
    float* __restrict__ out)
{
    __shared__ u64 zp2[64*8];        // Z row-pairs (row0,row1), fi pre-negated: 4 KB
    __shared__ u64 wp[64*32];        // dec1 weight pairs: [c][o/2] = (w[o,c],w[o+1,c]): 16 KB
    __shared__ u64 b1p[32], w2p[32];

    int w = threadIdx.x, b = blockIdx.y;
    int h0r = blockIdx.x * 2;

    for (int idx = w; idx < 2048; idx += 256) {
        int c = idx & 63, op = idx >> 6;
        wp[c*32 + op] = pk2(d1w[(2*op)*64 + c], d1w[(2*op+1)*64 + c]);
    }
    if (w < 32) {
        b1p[w] = pk2(d1b[2*w], d1b[2*w+1]);
        w2p[w] = pk2(d2w[2*w], d2w[2*w+1]);
    }
    {
        const float* zr0 = g_Z + (b*HH + h0r)*CH*8;
        for (int idx = w; idx < 512; idx += 256) {
            float va = zr0[idx], vb = zr0[idx + 512];
            int j = idx & 7;
            if (j == 2 || j == 4 || j == 6) { va = -va; vb = -vb; }
            zp2[idx] = pk2(va, vb);
        }
    }
    __syncthreads();

    float a = 6.28318530717958647692f * (1.0f/256.0f) * (float)w;
    float cy1, sy1; sincosf(a, &sy1, &cy1);
    float cy2 = cy1*cy1 - sy1*sy1, sy2 = 2.f*sy1*cy1;
    float cy3 = cy2*cy1 - sy2*sy1, sy3 = sy2*cy1 + cy2*sy1;
    u64 C1 = splat2(cy1), S1 = splat2(sy1);
    u64 C2 = splat2(cy2), S2 = splat2(sy2);
    u64 C3 = splat2(cy3), S3 = splat2(sy3);

    u64 accA[32], accB[32];
    #pragma unroll
    for (int k = 0; k < 32; k++) { accA[k] = b1p[k]; accB[k] = b1p[k]; }

    const float* h0p = g_h0 + b*CH*HW + h0r*WW + w;
    #pragma unroll 4
    for (int c = 0; c < 64; c++) {
        float ha = h0p[c*HW];
        float hb = h0p[c*HW + WW];
        const ulonglong2* z2 = (const ulonglong2*)&zp2[c*8];
        ulonglong2 z01 = z2[0], z23 = z2[1], z45 = z2[2];
        u64 z6 = zp2[c*8 + 6];
        u64 hv2 = f2add(pk2(ha, hb), z01.x);
        hv2 = f2fma(z01.y, C1, hv2);
        hv2 = f2fma(z23.x, S1, hv2);
        hv2 = f2fma(z23.y, C2, hv2);
        hv2 = f2fma(z45.x, S2, hv2);
        hv2 = f2fma(z45.y, C3, hv2);
        hv2 = f2fma(z6,    S3, hv2);
        float2 hv = upk2(hv2);
        u64 hsA = splat2(hv.x), hsB = splat2(hv.y);
        const ulonglong2* wrow = (const ulonglong2*)&wp[c*32];
        #pragma unroll
        for (int k2 = 0; k2 < 16; k2++) {
            ulonglong2 wv = wrow[k2];
            accA[k2*2]   = f2fma(hsA, wv.x, accA[k2*2]);
            accA[k2*2+1] = f2fma(hsA, wv.y, accA[k2*2+1]);
            accB[k2*2]   = f2fma(hsB, wv.x, accB[k2*2]);
            accB[k2*2+1] = f2fma(hsB, wv.y, accB[k2*2+1]);
        }
    }

    u64 oaccA = splat2(0.f), oaccB = splat2(0.f);
    #pragma unroll
    for (int k = 0; k < 32; k++) {
        float2 va = upk2(accA[k]);
        float2 vb = upk2(accB[k]);
        u64 ta = pk2(fast_tanh(va.x), fast_tanh(va.y));
        u64 tb = pk2(fast_tanh(vb.x), fast_tanh(vb.y));
        oaccA = f2fma(ta, w2p[k], oaccA);
        oaccB = f2fma(tb, w2p[k], oaccB);
    }
    float2 oA = upk2(oaccA), oB = upk2(oaccB);
    float b2v = d2b[0];
    float* op = out + b*HW + h0r*WW + w;
    op[0]  = oA.x + oA.y + b2v;
    op[WW] = oB.x + oB.y + b2v;
}

extern "C" void kernel_launch(void* const* d_in, const int* in_sizes, int n_in,
                              void* d_out, int out_size)
{
    const float* x   = (const float*)d_in[0];
    const float* ew  = (const float*)d_in[1];
    const float* eb  = (const float*)d_in[2];
    const float* d1w = (const float*)d_in[3];
    const float* d1b = (const float*)d_in[4];
    const float* d2w = (const float*)d_in[5];
    const float* d2b = (const float*)d_in[6];
    const float* w1r = (const float*)d_in[7];
    const float* w1i = (const float*)d_in[8];
    const float* w2r = (const float*)d_in[9];
    const float* w2i = (const float*)d_in[10];
    float* out = (float*)d_out;

    cudaFuncSetAttribute(k_mix6, cudaFuncAttributeMaxDynamicSharedMemorySize, 65536);

    k_repack<<<32, 256>>>(w1r, w1i, w2r, w2i);
    k_encode<<<dim3(256, 8), 256>>>(x, ew, eb);
    k_project<<<dim3(64, 8), 256>>>();
    k_mix6<<<dim3(29, 8), 128, 65536>>>();
    k_ztable<<<dim3(64, 8), 256>>>();
    k_final<<<dim3(128, 8), 256>>>(d1w, d1b, d2w, d2b, out);
}

// round 6
// speedup vs baseline: 1.1302x; 1.1302x over previous
#include <cuda_runtime.h>
#include <math.h>

#define BB 8
#define CH 64
#define HH 256
#define WW 256
#define HW 65536

typedef unsigned long long u64;

__device__ __forceinline__ u64 pk2(float lo, float hi){ u64 r; asm("mov.b64 %0,{%1,%2};" : "=l"(r) : "f"(lo), "f"(hi)); return r; }
__device__ __forceinline__ u64 splat2(float v){ u64 r; asm("mov.b64 %0,{%1,%1};" : "=l"(r) : "f"(v)); return r; }
__device__ __forceinline__ float2 upk2(u64 a){ float2 f; asm("mov.b64 {%0,%1},%2;" : "=f"(f.x), "=f"(f.y) : "l"(a)); return f; }
__device__ __forceinline__ u64 f2fma(u64 a, u64 b, u64 c){ u64 d; asm("fma.rn.f32x2 %0,%1,%2,%3;" : "=l"(d) : "l"(a), "l"(b), "l"(c)); return d; }

// fast tanh: 1 - 2/(1+2^(x*2*log2 e)). MUFU EX2 + MUFU RCP, ~1e-6 abs err,
// exact saturation at +/-inf.
__device__ __forceinline__ float fast_tanh(float x){
    float e, r;
    asm("ex2.approx.f32 %0, %1;" : "=f"(e) : "f"(x * 2.8853900817779268f));
    asm("rcp.approx.f32 %0, %1;" : "=f"(r) : "f"(e + 1.0f));
    return fmaf(-2.0f, r, 1.0f);
}

// Scratch (device globals: no allocation allowed)
__device__ float g_h0[BB*CH*HW];      // 2*tanh(enc) field (134 MB)
__device__ float g_v [BB*CH*64];      // projected modes [b][c][kxi*8+ky*2+{re,im}]
__device__ float g_gA[BB*CH*64];      // final mode state after 6 iterations
__device__ float g_Z [BB*HH*CH*8];    // per-row recon coeffs [b][h][c][f0,fr1,fi1,fr2,fi2,fr3,fi3,pad]
__device__ float g_wre[32*4096];      // repacked mix weights [slice][i*64+o]
__device__ float g_wim[32*4096];

// ---------------------------------------------------------------------------
// K0: repack spectral weights. slice s = kxi*4+ky; entry i*64+o.
// ---------------------------------------------------------------------------
__global__ void k_repack(const float* __restrict__ w1r, const float* __restrict__ w1i,
                         const float* __restrict__ w2r, const float* __restrict__ w2i)
{
    int s = blockIdx.x;
    int kxi = s >> 2, ky = s & 3;
    const float* srcr = (kxi < 4) ? w1r : w2r;
    const float* srci = (kxi < 4) ? w1i : w2i;
    int kk = (kxi & 3) * 4 + ky;
    for (int idx = threadIdx.x; idx < 4096; idx += blockDim.x) {
        g_wre[s*4096 + idx] = srcr[idx*16 + kk];
        g_wim[s*4096 + idx] = srci[idx*16 + kk];
    }
}

// ---------------------------------------------------------------------------
// K1: encoder  h0 = 2*tanh(enc_w @ x + enc_b)   (skip 2x folded here)
// ---------------------------------------------------------------------------
__global__ void k_encode(const float* __restrict__ x,
                         const float* __restrict__ ew,
                         const float* __restrict__ eb)
{
    __shared__ float sw[192];
    __shared__ float sb[64];
    int t = threadIdx.x;
    if (t < 192) sw[t] = ew[t];
    if (t < 64)  sb[t] = eb[t];
    __syncthreads();

    int w = t, h = blockIdx.x, b = blockIdx.y;
    const float* xp = x + ((b*3)*HH + h)*WW + w;
    float x0 = xp[0], x1 = xp[HW], x2 = xp[2*HW];
    float* hp = g_h0 + (b*CH*HH + h)*WW + w;
    #pragma unroll 8
    for (int c = 0; c < CH; c++) {
        float v = fmaf(sw[3*c], x0, fmaf(sw[3*c+1], x1, fmaf(sw[3*c+2], x2, sb[c])));
        hp[c*HW] = 2.f * fast_tanh(v);
    }
}

// ---------------------------------------------------------------------------
// K2: projection v = P h0 (scaled 2x since h0 is doubled; folded out in K4).
// ---------------------------------------------------------------------------
__global__ void k_project()
{
    __shared__ float ph[256][8];
    __shared__ float red[8][64];
    int w = threadIdx.x, c = blockIdx.x, b = blockIdx.y;

    float a = 6.28318530717958647692f * (1.0f/256.0f) * (float)w;
    float c1, s1; sincosf(a, &s1, &c1);
    float c2 = c1*c1 - s1*s1,  s2 = 2.f*s1*c1;
    float c3 = c2*c1 - s2*s1,  s3 = s2*c1 + c2*s1;
    float c4 = c2*c2 - s2*s2,  s4 = 2.f*s2*c2;
    ph[w][0]=c1; ph[w][1]=s1; ph[w][2]=c2; ph[w][3]=s2;
    ph[w][4]=c3; ph[w][5]=s3; ph[w][6]=c4; ph[w][7]=s4;
    __syncthreads();

    const float* hp = g_h0 + (b*CH + c)*HW + w;
    float a0=0.f, ar1=0.f, b1=0.f, ar2=0.f, b2=0.f, ar3=0.f, b3=0.f, ar4=0.f, b4=0.f;
    #pragma unroll 4
    for (int hh = 0; hh < 256; hh++) {
        float v = hp[hh*256];
        float4 p0 = *(const float4*)&ph[hh][0];
        float4 p1 = *(const float4*)&ph[hh][4];
        a0 += v;
        ar1 = fmaf(v, p0.x, ar1);  b1 = fmaf(v, p0.y, b1);
        ar2 = fmaf(v, p0.z, ar2);  b2 = fmaf(v, p0.w, b2);
        ar3 = fmaf(v, p1.x, ar3);  b3 = fmaf(v, p1.y, b3);
        ar4 = fmaf(v, p1.z, ar4);  b4 = fmaf(v, p1.w, b4);
    }

    float crr[8] = {a0,  ar1, ar2, ar3, ar4, ar3, ar2, ar1};
    float cii[8] = {0.f, -b1, -b2, -b3,  b4,  b3,  b2,  b1};
    float cyk[4] = {1.f, c1, c2, c3};
    float syk[4] = {0.f, s1, s2, s3};

    int lane = w & 31, wid = w >> 5;
    #pragma unroll
    for (int kxi = 0; kxi < 8; kxi++) {
        #pragma unroll
        for (int ky = 0; ky < 4; ky++) {
            float re = crr[kxi]*cyk[ky] + cii[kxi]*syk[ky];
            float im = cii[kxi]*cyk[ky] - crr[kxi]*syk[ky];
            #pragma unroll
            for (int o = 16; o > 0; o >>= 1) {
                re += __shfl_xor_sync(0xffffffffu, re, o);
                im += __shfl_xor_sync(0xffffffffu, im, o);
            }
            if (lane == 0) {
                red[wid][(kxi*4+ky)*2    ] = re;
                red[wid][(kxi*4+ky)*2 + 1] = im;
            }
        }
    }
    __syncthreads();
    if (w < 64) {
        float s = 0.f;
        #pragma unroll
        for (int q = 0; q < 8; q++) s += red[q][w];
        g_v[(b*CH + c)*64 + w] = s;
    }
}

// ---------------------------------------------------------------------------
// K3: ALL 6 mode-space iterations fused.
// ---------------------------------------------------------------------------
__global__ void __launch_bounds__(128) k_mix6()
{
    extern __shared__ float smw[];
    float* swr = smw;          // [2][4096]
    float* swi = smw + 8192;
    __shared__ float vr[2][64], vi[2][64], gr[2][64], gi[2][64], fr[2][64], fi[2][64];

    int g = blockIdx.x, b = blockIdx.y, tid = threadIdx.x;
    int s0, s1 = -1, tmode;
    if (g < 24)      { int kxi=g/3, ky=g%3+1; s0=kxi*4+ky; tmode=0; }
    else if (g==24)  { s0=0;           tmode=1; }
    else if (g==25)  { s0=16;          tmode=2; }
    else if (g==26)  { s0=4;  s1=28;   tmode=3; }
    else if (g==27)  { s0=8;  s1=24;   tmode=3; }
    else             { s0=12; s1=20;   tmode=3; }
    int nsl = (s1 >= 0) ? 2 : 1;

    for (int q = 0; q < nsl; q++) {
        int s = q ? s1 : s0;
        for (int idx = tid; idx < 4096; idx += 128) {
            swr[q*4096 + idx] = g_wre[s*4096 + idx];
            swi[q*4096 + idx] = g_wim[s*4096 + idx];
        }
    }
    int sl = tid >> 6, o = tid & 63;
    if (sl < nsl) {
        int s = sl ? s1 : s0;
        int base = (b*64 + o)*64 + s*2;
        vr[sl][o] = g_v[base]; vi[sl][o] = g_v[base+1];
    }
    __syncthreads();

    for (int it = 0; it < 6; it++) {
        if (sl < nsl) {
            float tr = 0.f, ti = 0.f;
            if (it > 0) {
                float grv = gr[sl][o], giv = gi[sl][o];
                if      (tmode == 0) { tr = grv;       ti = giv; }
                else if (tmode == 1) { tr = grv;       ti = 0.f; }
                else if (tmode == 2) { tr = 0.5f*grv;  ti = 0.5f*giv; }
                else { tr = 0.5f*(grv + gr[1-sl][o]);  ti = 0.5f*(giv - gi[1-sl][o]); }
            }
            fr[sl][o] = vr[sl][o] + tr;
            fi[sl][o] = vi[sl][o] + ti;
        }
        __syncthreads();
        float accr = 0.f, acci = 0.f;
        if (sl < nsl) {
            const float* wrp = swr + sl*4096;
            const float* wip = swi + sl*4096;
            #pragma unroll 8
            for (int i = 0; i < 64; i++) {
                float w_r = wrp[i*64 + o], w_i = wip[i*64 + o];
                float f_r = fr[sl][i],     f_i = fi[sl][i];
                accr = fmaf(f_r, w_r, accr); accr = fmaf(-f_i, w_i, accr);
                acci = fmaf(f_r, w_i, acci); acci = fmaf( f_i, w_r, acci);
            }
        }
        __syncthreads();
        if (sl < nsl) {
            float g0r = it ? gr[sl][o] : 0.f;
            float g0i = it ? gi[sl][o] : 0.f;
            gr[sl][o] = g0r + accr;
            gi[sl][o] = g0i + acci;
        }
        __syncthreads();
    }

    if (sl < nsl) {
        int s = sl ? s1 : s0;
        int base = (b*64 + o)*64 + s*2;
        g_gA[base]   = gr[sl][o];
        g_gA[base+1] = gi[sl][o];
    }
}

// ---------------------------------------------------------------------------
// K4: per-row reconstruction coefficients (0.5 folded for doubled h0).
// ---------------------------------------------------------------------------
__global__ void k_ztable()
{
    __shared__ float gm[64];
    int h = threadIdx.x, c = blockIdx.x, b = blockIdx.y;
    if (h < 64) gm[h] = g_gA[(b*CH + c)*64 + h];
    __syncthreads();

    float a = 6.28318530717958647692f * (1.0f/256.0f) * (float)h;
    float c1, s1; sincosf(a, &s1, &c1);
    float c2 = c1*c1 - s1*s1,  s2 = 2.f*s1*c1;
    float c3 = c2*c1 - s2*s1,  s3 = s2*c1 + c2*s1;
    float c4 = c2*c2 - s2*s2,  s4 = 2.f*s2*c2;
    float pc[8] = {1.f, c1, c2, c3,  c4,  c3,  c2,  c1};
    float ps[8] = {0.f, s1, s2, s3, -s4, -s3, -s2, -s1};

    float outv[8];
    #pragma unroll
    for (int ky = 0; ky < 4; ky++) {
        float zr = 0.f, zi = 0.f;
        #pragma unroll
        for (int kxi = 0; kxi < 8; kxi++) {
            float grv = gm[kxi*8 + ky*2], giv = gm[kxi*8 + ky*2 + 1];
            zr += grv*pc[kxi] - giv*ps[kxi];
            zi += grv*ps[kxi] + giv*pc[kxi];
        }
        if (ky == 0) outv[0] = zr * (1.f/131072.f);
        else { outv[ky*2-1] = zr * (1.f/65536.f);
               outv[ky*2  ] = zi * (1.f/65536.f); }
    }
    outv[7] = 0.f;

    float* zp = g_Z + ((b*HH + h)*CH + c)*8;
    #pragma unroll
    for (int j = 0; j < 8; j++) zp[j] = outv[j];
}

// ---------------------------------------------------------------------------
// K5: fused epilogue (R4 structure: 1 pixel/thread, 32 packed accs) +
// fast_tanh. f32x2 packed over output-channel pairs; weight pairs natural
// u64s in smem; hv transient in register.
// ---------------------------------------------------------------------------
__global__ void __launch_bounds__(256, 2) k_final(
    const float* __restrict__ d1w, const float* __restrict__ d1b,
    const float* __restrict__ d2w, const float* __restrict__ d2b,
    float* __restrict__ out)
{
    __shared__ float zs[512];        // Z row, fi pre-negated
    __shared__ u64 wp[64*32];        // dec1 weight pairs: [c][o/2] = (w[o,c], w[o+1,c])
    __shared__ u64 b1p[32], w2p[32];

    int w = threadIdx.x, h = blockIdx.x, b = blockIdx.y;

    for (int idx = w; idx < 2048; idx += 256) {
        int c = idx & 63, op = idx >> 6;
        wp[c*32 + op] = pk2(d1w[(2*op)*64 + c], d1w[(2*op+1)*64 + c]);
    }
    if (w < 32) {
        b1p[w] = pk2(d1b[2*w], d1b[2*w+1]);
        w2p[w] = pk2(d2w[2*w], d2w[2*w+1]);
    }
    {
        const float* zrow = g_Z + (b*HH + h)*CH*8;
        for (int idx = w; idx < 512; idx += 256) {
            float v = zrow[idx];
            int j = idx & 7;
            if (j == 2 || j == 4 || j == 6) v = -v;
            zs[idx] = v;
        }
    }
    __syncthreads();

    float a = 6.28318530717958647692f * (1.0f/256.0f) * (float)w;
    float cy1, sy1; sincosf(a, &sy1, &cy1);
    float cy2 = cy1*cy1 - sy1*sy1, sy2 = 2.f*sy1*cy1;
    float cy3 = cy2*cy1 - sy2*sy1, sy3 = sy2*cy1 + cy2*sy1;

    u64 acc[32];
    #pragma unroll
    for (int k = 0; k < 32; k++) acc[k] = b1p[k];

    const float* h0p = g_h0 + b*CH*HW + h*WW + w;
    #pragma unroll 4
    for (int c = 0; c < 64; c++) {
        float h0v = h0p[c*HW];
        float4 za = *(const float4*)&zs[c*8];      // f0, fr1, -fi1, fr2
        float4 zb = *(const float4*)&zs[c*8 + 4];  // -fi2, fr3, -fi3, 0
        float hvv = h0v + za.x;
        hvv = fmaf(za.y, cy1, hvv);
        hvv = fmaf(za.z, sy1, hvv);
        hvv = fmaf(za.w, cy2, hvv);
        hvv = fmaf(zb.x, sy2, hvv);
        hvv = fmaf(zb.y, cy3, hvv);
        hvv = fmaf(zb.z, sy3, hvv);
        u64 hs = splat2(hvv);
        const ulonglong2* wrow = (const ulonglong2*)&wp[c*32];
        #pragma unroll
        for (int k2 = 0; k2 < 16; k2++) {
            ulonglong2 wv = wrow[k2];
            acc[k2*2]   = f2fma(hs, wv.x, acc[k2*2]);
            acc[k2*2+1] = f2fma(hs, wv.y, acc[k2*2+1]);
        }
    }

    u64 oacc = splat2(0.f);
    #pragma unroll
    for (int k = 0; k < 32; k++) {
        float2 v = upk2(acc[k]);
        u64 tv = pk2(fast_tanh(v.x), fast_tanh(v.y));
        oacc = f2fma(tv, w2p[k], oacc);
    }
    float2 o2 = upk2(oacc);
    out[b*HW + h*WW + w] = o2.x + o2.y + d2b[0];
}

extern "C" void kernel_launch(void* const* d_in, const int* in_sizes, int n_in,
                              void* d_out, int out_size)
{
    const float* x   = (const float*)d_in[0];
    const float* ew  = (const float*)d_in[1];
    const float* eb  = (const float*)d_in[2];
    const float* d1w = (const float*)d_in[3];
    const float* d1b = (const float*)d_in[4];
    const float* d2w = (const float*)d_in[5];
    const float* d2b = (const float*)d_in[6];
    const float* w1r = (const float*)d_in[7];
    const float* w1i = (const float*)d_in[8];
    const float* w2r = (const float*)d_in[9];
    const float* w2i = (const float*)d_in[10];
    float* out = (float*)d_out;

    cudaFuncSetAttribute(k_mix6, cudaFuncAttributeMaxDynamicSharedMemorySize, 65536);

    k_repack<<<32, 256>>>(w1r, w1i, w2r, w2i);
    k_encode<<<dim3(256, 8), 256>>>(x, ew, eb);
    k_project<<<dim3(64, 8), 256>>>();
    k_mix6<<<dim3(29, 8), 128, 65536>>>();
    k_ztable<<<dim3(64, 8), 256>>>();
    k_final<<<dim3(256, 8), 256>>>(d1w, d1b, d2w, d2b, out);
}

// round 7
// speedup vs baseline: 1.2826x; 1.1348x over previous
#include <cuda_runtime.h>
#include <math.h>

#define BB 8
#define CH 64
#define HH 256
#define WW 256
#define HW 65536

typedef unsigned long long u64;

__device__ __forceinline__ u64 pk2(float lo, float hi){ u64 r; asm("mov.b64 %0,{%1,%2};" : "=l"(r) : "f"(lo), "f"(hi)); return r; }
__device__ __forceinline__ u64 splat2(float v){ u64 r; asm("mov.b64 %0,{%1,%1};" : "=l"(r) : "f"(v)); return r; }
__device__ __forceinline__ float2 upk2(u64 a){ float2 f; asm("mov.b64 {%0,%1},%2;" : "=f"(f.x), "=f"(f.y) : "l"(a)); return f; }
__device__ __forceinline__ u64 f2fma(u64 a, u64 b, u64 c){ u64 d; asm("fma.rn.f32x2 %0,%1,%2,%3;" : "=l"(d) : "l"(a), "l"(b), "l"(c)); return d; }

// fast tanh: 1 - 2/(1+2^(x*2*log2 e)). MUFU EX2 + MUFU RCP, ~1e-6 abs err.
__device__ __forceinline__ float fast_tanh(float x){
    float e, r;
    asm("ex2.approx.f32 %0, %1;" : "=f"(e) : "f"(x * 2.8853900817779268f));
    asm("rcp.approx.f32 %0, %1;" : "=f"(r) : "f"(e + 1.0f));
    return fmaf(-2.0f, r, 1.0f);
}
// 2*tanh via rcp of (1+exp2): caller applies fmaf(-4, r, 2 + base)
__device__ __forceinline__ float tanh_rcp(float x){
    float e, r;
    asm("ex2.approx.f32 %0, %1;" : "=f"(e) : "f"(x * 2.8853900817779268f));
    asm("rcp.approx.f32 %0, %1;" : "=f"(r) : "f"(e + 1.0f));
    return r;
}

// Scratch (device globals: no allocation allowed). NO h0 field anymore.
__device__ float g_v [BB*CH*64];      // projected modes [b][c][kxi*8+ky*2+{re,im}]
__device__ float g_gA[BB*CH*64];      // final mode state after 6 iterations
__device__ float g_Z [BB*HH*CH*8];    // per-row recon coeffs
__device__ float g_wre[32*4096];      // repacked mix weights [slice][i*64+o]
__device__ float g_wim[32*4096];

// ---------------------------------------------------------------------------
// K0: repack spectral weights. slice s = kxi*4+ky; entry i*64+o.
// ---------------------------------------------------------------------------
__global__ void k_repack(const float* __restrict__ w1r, const float* __restrict__ w1i,
                         const float* __restrict__ w2r, const float* __restrict__ w2i)
{
    int s = blockIdx.x;
    int kxi = s >> 2, ky = s & 3;
    const float* srcr = (kxi < 4) ? w1r : w2r;
    const float* srci = (kxi < 4) ? w1i : w2i;
    int kk = (kxi & 3) * 4 + ky;
    for (int idx = threadIdx.x; idx < 4096; idx += blockDim.x) {
        g_wre[s*4096 + idx] = srcr[idx*16 + kk];
        g_wim[s*4096 + idx] = srci[idx*16 + kk];
    }
}

// ---------------------------------------------------------------------------
// K2: projection v = P (2*tanh(enc(x))), h0 recomputed on the fly from x
// (x is 6 MB -> L2 resident). block=(w)=256, grid=(c, b).
// ---------------------------------------------------------------------------
__global__ void __launch_bounds__(256) k_project(
    const float* __restrict__ x,
    const float* __restrict__ ew,
    const float* __restrict__ eb)
{
    __shared__ float ph[256][8];   // per-h phases c1,s1,c2,s2,c3,s3,c4,s4
    __shared__ float red[8][64];
    int w = threadIdx.x, c = blockIdx.x, b = blockIdx.y;
    __shared__ float we0, we1, we2, web;
    if (w == 0) { we0 = ew[3*c]; we1 = ew[3*c+1]; we2 = ew[3*c+2]; web = eb[c]; }

    float a = 6.28318530717958647692f * (1.0f/256.0f) * (float)w;
    float c1, s1; sincosf(a, &s1, &c1);
    float c2 = c1*c1 - s1*s1,  s2 = 2.f*s1*c1;
    float c3 = c2*c1 - s2*s1,  s3 = s2*c1 + c2*s1;
    float c4 = c2*c2 - s2*s2,  s4 = 2.f*s2*c2;
    ph[w][0]=c1; ph[w][1]=s1; ph[w][2]=c2; ph[w][3]=s2;
    ph[w][4]=c3; ph[w][5]=s3; ph[w][6]=c4; ph[w][7]=s4;
    __syncthreads();

    float e0 = we0, e1 = we1, e2 = we2, ebv = web;
    const float* xp = x + (b*3)*HW + w;
    float a0=0.f, ar1=0.f, b1=0.f, ar2=0.f, b2=0.f, ar3=0.f, b3=0.f, ar4=0.f, b4=0.f;
    #pragma unroll 4
    for (int hh = 0; hh < 256; hh++) {
        float x0 = xp[hh*256], x1 = xp[hh*256 + HW], x2 = xp[hh*256 + 2*HW];
        float pre = fmaf(e0, x0, fmaf(e1, x1, fmaf(e2, x2, ebv)));
        float r = tanh_rcp(pre);
        float v = fmaf(-4.f, r, 2.f);     // 2*tanh
        float4 p0 = *(const float4*)&ph[hh][0];
        float4 p1 = *(const float4*)&ph[hh][4];
        a0 += v;
        ar1 = fmaf(v, p0.x, ar1);  b1 = fmaf(v, p0.y, b1);
        ar2 = fmaf(v, p0.z, ar2);  b2 = fmaf(v, p0.w, b2);
        ar3 = fmaf(v, p1.x, ar3);  b3 = fmaf(v, p1.y, b3);
        ar4 = fmaf(v, p1.z, ar4);  b4 = fmaf(v, p1.w, b4);
    }

    float crr[8] = {a0,  ar1, ar2, ar3, ar4, ar3, ar2, ar1};
    float cii[8] = {0.f, -b1, -b2, -b3,  b4,  b3,  b2,  b1};
    float cyk[4] = {1.f, c1, c2, c3};
    float syk[4] = {0.f, s1, s2, s3};

    int lane = w & 31, wid = w >> 5;
    #pragma unroll
    for (int kxi = 0; kxi < 8; kxi++) {
        #pragma unroll
        for (int ky = 0; ky < 4; ky++) {
            float re = crr[kxi]*cyk[ky] + cii[kxi]*syk[ky];
            float im = cii[kxi]*cyk[ky] - crr[kxi]*syk[ky];
            #pragma unroll
            for (int o = 16; o > 0; o >>= 1) {
                re += __shfl_xor_sync(0xffffffffu, re, o);
                im += __shfl_xor_sync(0xffffffffu, im, o);
            }
            if (lane == 0) {
                red[wid][(kxi*4+ky)*2    ] = re;
                red[wid][(kxi*4+ky)*2 + 1] = im;
            }
        }
    }
    __syncthreads();
    if (w < 64) {
        float s = 0.f;
        #pragma unroll
        for (int q = 0; q < 8; q++) s += red[q][w];
        g_v[(b*CH + c)*64 + w] = s;
    }
}

// ---------------------------------------------------------------------------
// K3: ALL 6 mode-space iterations fused.
// ---------------------------------------------------------------------------
__global__ void __launch_bounds__(128) k_mix6()
{
    extern __shared__ float smw[];
    float* swr = smw;          // [2][4096]
    float* swi = smw + 8192;
    __shared__ float vr[2][64], vi[2][64], gr[2][64], gi[2][64], fr[2][64], fi[2][64];

    int g = blockIdx.x, b = blockIdx.y, tid = threadIdx.x;
    int s0, s1 = -1, tmode;
    if (g < 24)      { int kxi=g/3, ky=g%3+1; s0=kxi*4+ky; tmode=0; }
    else if (g==24)  { s0=0;           tmode=1; }
    else if (g==25)  { s0=16;          tmode=2; }
    else if (g==26)  { s0=4;  s1=28;   tmode=3; }
    else if (g==27)  { s0=8;  s1=24;   tmode=3; }
    else             { s0=12; s1=20;   tmode=3; }
    int nsl = (s1 >= 0) ? 2 : 1;

    for (int q = 0; q < nsl; q++) {
        int s = q ? s1 : s0;
        for (int idx = tid; idx < 4096; idx += 128) {
            swr[q*4096 + idx] = g_wre[s*4096 + idx];
            swi[q*4096 + idx] = g_wim[s*4096 + idx];
        }
    }
    int sl = tid >> 6, o = tid & 63;
    if (sl < nsl) {
        int s = sl ? s1 : s0;
        int base = (b*64 + o)*64 + s*2;
        vr[sl][o] = g_v[base]; vi[sl][o] = g_v[base+1];
    }
    __syncthreads();

    for (int it = 0; it < 6; it++) {
        if (sl < nsl) {
            float tr = 0.f, ti = 0.f;
            if (it > 0) {
                float grv = gr[sl][o], giv = gi[sl][o];
                if      (tmode == 0) { tr = grv;       ti = giv; }
                else if (tmode == 1) { tr = grv;       ti = 0.f; }
                else if (tmode == 2) { tr = 0.5f*grv;  ti = 0.5f*giv; }
                else { tr = 0.5f*(grv + gr[1-sl][o]);  ti = 0.5f*(giv - gi[1-sl][o]); }
            }
            fr[sl][o] = vr[sl][o] + tr;
            fi[sl][o] = vi[sl][o] + ti;
        }
        __syncthreads();
        float accr = 0.f, acci = 0.f;
        if (sl < nsl) {
            const float* wrp = swr + sl*4096;
            const float* wip = swi + sl*4096;
            #pragma unroll 8
            for (int i = 0; i < 64; i++) {
                float w_r = wrp[i*64 + o], w_i = wip[i*64 + o];
                float f_r = fr[sl][i],     f_i = fi[sl][i];
                accr = fmaf(f_r, w_r, accr); accr = fmaf(-f_i, w_i, accr);
                acci = fmaf(f_r, w_i, acci); acci = fmaf( f_i, w_r, acci);
            }
        }
        __syncthreads();
        if (sl < nsl) {
            float g0r = it ? gr[sl][o] : 0.f;
            float g0i = it ? gi[sl][o] : 0.f;
            gr[sl][o] = g0r + accr;
            gi[sl][o] = g0i + acci;
        }
        __syncthreads();
    }

    if (sl < nsl) {
        int s = sl ? s1 : s0;
        int base = (b*64 + o)*64 + s*2;
        g_gA[base]   = gr[sl][o];
        g_gA[base+1] = gi[sl][o];
    }
}

// ---------------------------------------------------------------------------
// K4: per-row reconstruction coefficients (0.5 folded for doubled h0).
// ---------------------------------------------------------------------------
__global__ void k_ztable()
{
    __shared__ float gm[64];
    int h = threadIdx.x, c = blockIdx.x, b = blockIdx.y;
    if (h < 64) gm[h] = g_gA[(b*CH + c)*64 + h];
    __syncthreads();

    float a = 6.28318530717958647692f * (1.0f/256.0f) * (float)h;
    float c1, s1; sincosf(a, &s1, &c1);
    float c2 = c1*c1 - s1*s1,  s2 = 2.f*s1*c1;
    float c3 = c2*c1 - s2*s1,  s3 = s2*c1 + c2*s1;
    float c4 = c2*c2 - s2*s2,  s4 = 2.f*s2*c2;
    float pc[8] = {1.f, c1, c2, c3,  c4,  c3,  c2,  c1};
    float ps[8] = {0.f, s1, s2, s3, -s4, -s3, -s2, -s1};

    float outv[8];
    #pragma unroll
    for (int ky = 0; ky < 4; ky++) {
        float zr = 0.f, zi = 0.f;
        #pragma unroll
        for (int kxi = 0; kxi < 8; kxi++) {
            float grv = gm[kxi*8 + ky*2], giv = gm[kxi*8 + ky*2 + 1];
            zr += grv*pc[kxi] - giv*ps[kxi];
            zi += grv*ps[kxi] + giv*pc[kxi];
        }
        if (ky == 0) outv[0] = zr * (1.f/131072.f);
        else { outv[ky*2-1] = zr * (1.f/65536.f);
               outv[ky*2  ] = zi * (1.f/65536.f); }
    }
    outv[7] = 0.f;

    float* zp = g_Z + ((b*HH + h)*CH + c)*8;
    #pragma unroll
    for (int j = 0; j < 8; j++) zp[j] = outv[j];
}

// ---------------------------------------------------------------------------
// K5: fused epilogue. h0 term RECOMPUTED from x (3 LDG/pixel instead of 64):
// per c: LDS.128 of packed enc (w0,w1,w2,b) + 5 FMA + 2 MUFU + 7 recon FMA,
// then 32 FFMA2 vs paired dec1 weights. 1 px/thread, 32 packed accs.
// ---------------------------------------------------------------------------
__global__ void __launch_bounds__(256, 2) k_final(
    const float* __restrict__ x,
    const float* __restrict__ ew, const float* __restrict__ eb,
    const float* __restrict__ d1w, const float* __restrict__ d1b,
    const float* __restrict__ d2w, const float* __restrict__ d2b,
    float* __restrict__ out)
{
    __shared__ float zs[512];        // Z row, fi pre-negated, f0 biased +2? (no: +2 folded at use)
    __shared__ float4 wenc[64];      // (ew0, ew1, ew2, eb) per channel
    __shared__ u64 wp[64*32];        // dec1 weight pairs
    __shared__ u64 b1p[32], w2p[32];

    int w = threadIdx.x, h = blockIdx.x, b = blockIdx.y;

    for (int idx = w; idx < 2048; idx += 256) {
        int c = idx & 63, op = idx >> 6;
        wp[c*32 + op] = pk2(d1w[(2*op)*64 + c], d1w[(2*op+1)*64 + c]);
    }
    if (w < 32) {
        b1p[w] = pk2(d1b[2*w], d1b[2*w+1]);
        w2p[w] = pk2(d2w[2*w], d2w[2*w+1]);
    }
    if (w < 64) wenc[w] = make_float4(ew[3*w], ew[3*w+1], ew[3*w+2], eb[w]);
    {
        const float* zrow = g_Z + (b*HH + h)*CH*8;
        for (int idx = w; idx < 512; idx += 256) {
            float v = zrow[idx];
            int j = idx & 7;
            if (j == 2 || j == 4 || j == 6) v = -v;
            if (j == 0) v += 2.f;            // fold the "+2" of 2*tanh into f0
            zs[idx] = v;
        }
    }
    __syncthreads();

    float a = 6.28318530717958647692f * (1.0f/256.0f) * (float)w;
    float cy1, sy1; sincosf(a, &sy1, &cy1);
    float cy2 = cy1*cy1 - sy1*sy1, sy2 = 2.f*sy1*cy1;
    float cy3 = cy2*cy1 - sy2*sy1, sy3 = sy2*cy1 + cy2*sy1;

    const float* xp = x + (b*3)*HW + h*WW + w;
    float x0 = xp[0], x1 = xp[HW], x2 = xp[2*HW];

    u64 acc[32];
    #pragma unroll
    for (int k = 0; k < 32; k++) acc[k] = b1p[k];

    #pragma unroll 4
    for (int c = 0; c < 64; c++) {
        float4 we = wenc[c];
        float pre = fmaf(we.x, x0, fmaf(we.y, x1, fmaf(we.z, x2, we.w)));
        float r = tanh_rcp(pre);
        float4 za = *(const float4*)&zs[c*8];      // f0+2, fr1, -fi1, fr2
        float4 zb = *(const float4*)&zs[c*8 + 4];  // -fi2, fr3, -fi3, 0
        float hvv = fmaf(-4.f, r, za.x);           // 2*tanh + f0
        hvv = fmaf(za.y, cy1, hvv);
        hvv = fmaf(za.z, sy1, hvv);
        hvv = fmaf(za.w, cy2, hvv);
        hvv = fmaf(zb.x, sy2, hvv);
        hvv = fmaf(zb.y, cy3, hvv);
        hvv = fmaf(zb.z, sy3, hvv);
        u64 hs = splat2(hvv);
        const ulonglong2* wrow = (const ulonglong2*)&wp[c*32];
        #pragma unroll
        for (int k2 = 0; k2 < 16; k2++) {
            ulonglong2 wv = wrow[k2];
            acc[k2*2]   = f2fma(hs, wv.x, acc[k2*2]);
            acc[k2*2+1] = f2fma(hs, wv.y, acc[k2*2+1]);
        }
    }

    u64 oacc = splat2(0.f);
    #pragma unroll
    for (int k = 0; k < 32; k++) {
        float2 v = upk2(acc[k]);
        u64 tv = pk2(fast_tanh(v.x), fast_tanh(v.y));
        oacc = f2fma(tv, w2p[k], oacc);
    }
    float2 o2 = upk2(oacc);
    out[b*HW + h*WW + w] = o2.x + o2.y + d2b[0];
}

extern "C" void kernel_launch(void* const* d_in, const int* in_sizes, int n_in,
                              void* d_out, int out_size)
{
    const float* x   = (const float*)d_in[0];
    const float* ew  = (const float*)d_in[1];
    const float* eb  = (const float*)d_in[2];
    const float* d1w = (const float*)d_in[3];
    const float* d1b = (const float*)d_in[4];
    const float* d2w = (const float*)d_in[5];
    const float* d2b = (const float*)d_in[6];
    const float* w1r = (const float*)d_in[7];
    const float* w1i = (const float*)d_in[8];
    const float* w2r = (const float*)d_in[9];
    const float* w2i = (const float*)d_in[10];
    float* out = (float*)d_out;

    cudaFuncSetAttribute(k_mix6, cudaFuncAttributeMaxDynamicSharedMemorySize, 65536);

    k_repack<<<32, 256>>>(w1r, w1i, w2r, w2i);
    k_project<<<dim3(64, 8), 256>>>(x, ew, eb);
    k_mix6<<<dim3(29, 8), 128, 65536>>>();
    k_ztable<<<dim3(64, 8), 256>>>();
    k_final<<<dim3(256, 8), 256>>>(x, ew, eb, d1w, d1b, d2w, d2b, out);
}

// round 9
// speedup vs baseline: 1.3584x; 1.0592x over previous
#include <cuda_runtime.h>
#include <math.h>
#include <stdint.h>

#define BB 8
#define CH 64
#define HH 256
#define WW 256
#define HW 65536

typedef unsigned long long u64;

__device__ __forceinline__ u64 pk2(float lo, float hi){ u64 r; asm("mov.b64 %0,{%1,%2};" : "=l"(r) : "f"(lo), "f"(hi)); return r; }
__device__ __forceinline__ u64 splat2(float v){ u64 r; asm("mov.b64 %0,{%1,%1};" : "=l"(r) : "f"(v)); return r; }
__device__ __forceinline__ float2 upk2(u64 a){ float2 f; asm("mov.b64 {%0,%1},%2;" : "=f"(f.x), "=f"(f.y) : "l"(a)); return f; }
__device__ __forceinline__ u64 f2fma(u64 a, u64 b, u64 c){ u64 d; asm("fma.rn.f32x2 %0,%1,%2,%3;" : "=l"(d) : "l"(a), "l"(b), "l"(c)); return d; }

__device__ __forceinline__ float fast_tanh(float x){
    float e, r;
    asm("ex2.approx.f32 %0, %1;" : "=f"(e) : "f"(x * 2.8853900817779268f));
    asm("rcp.approx.f32 %0, %1;" : "=f"(r) : "f"(e + 1.0f));
    return fmaf(-2.0f, r, 1.0f);
}
__device__ __forceinline__ float tanh_rcp(float x){
    float e, r;
    asm("ex2.approx.f32 %0, %1;" : "=f"(e) : "f"(x * 2.8853900817779268f));
    asm("rcp.approx.f32 %0, %1;" : "=f"(r) : "f"(e + 1.0f));
    return r;
}

// Scratch
__device__ float g_v [BB*CH*64];
__device__ float g_gA[BB*CH*64];
__device__ float g_wre[32*4096];
__device__ float g_wim[32*4096];

// ---------------------------------------------------------------------------
// K0: repack spectral weights.
// ---------------------------------------------------------------------------
__global__ void k_repack(const float* __restrict__ w1r, const float* __restrict__ w1i,
                         const float* __restrict__ w2r, const float* __restrict__ w2i)
{
    int s = blockIdx.x;
    int kxi = s >> 2, ky = s & 3;
    const float* srcr = (kxi < 4) ? w1r : w2r;
    const float* srci = (kxi < 4) ? w1i : w2i;
    int kk = (kxi & 3) * 4 + ky;
    for (int idx = threadIdx.x; idx < 4096; idx += blockDim.x) {
        g_wre[s*4096 + idx] = srcr[idx*16 + kk];
        g_wim[s*4096 + idx] = srci[idx*16 + kk];
    }
}

// ---------------------------------------------------------------------------
// K2: projection, 2 CHANNELS per block (x triple loaded once serves both).
// grid = (32, 8), block = 256.
// ---------------------------------------------------------------------------
__global__ void __launch_bounds__(256) k_project(
    const float* __restrict__ x,
    const float* __restrict__ ew,
    const float* __restrict__ eb)
{
    __shared__ float ph[256][8];
    __shared__ float red[8][64];
    __shared__ float4 wenc2[2];
    int w = threadIdx.x, cg = blockIdx.x, b = blockIdx.y;
    int c0 = cg * 2;
    if (w < 2) wenc2[w] = make_float4(ew[3*(c0+w)], ew[3*(c0+w)+1], ew[3*(c0+w)+2], eb[c0+w]);

    float a = 6.28318530717958647692f * (1.0f/256.0f) * (float)w;
    float c1, s1; sincosf(a, &s1, &c1);
    float c2 = c1*c1 - s1*s1,  s2 = 2.f*s1*c1;
    float c3 = c2*c1 - s2*s1,  s3 = s2*c1 + c2*s1;
    float c4 = c2*c2 - s2*s2,  s4 = 2.f*s2*c2;
    ph[w][0]=c1; ph[w][1]=s1; ph[w][2]=c2; ph[w][3]=s2;
    ph[w][4]=c3; ph[w][5]=s3; ph[w][6]=c4; ph[w][7]=s4;
    __syncthreads();

    float4 weA = wenc2[0], weB = wenc2[1];
    const float* xp = x + (b*3)*HW + w;
    // accumulators: [ch][9]
    float A0[2]={0,0}, AR1[2]={0,0}, B1[2]={0,0}, AR2[2]={0,0}, B2[2]={0,0},
          AR3[2]={0,0}, B3[2]={0,0}, AR4[2]={0,0}, B4[2]={0,0};
    #pragma unroll 2
    for (int hh = 0; hh < 256; hh++) {
        float x0 = xp[hh*256], x1 = xp[hh*256 + HW], x2 = xp[hh*256 + 2*HW];
        float4 p0 = *(const float4*)&ph[hh][0];
        float4 p1 = *(const float4*)&ph[hh][4];
        {
            float pre = fmaf(weA.x, x0, fmaf(weA.y, x1, fmaf(weA.z, x2, weA.w)));
            float v = fmaf(-4.f, tanh_rcp(pre), 2.f);
            A0[0] += v;
            AR1[0] = fmaf(v, p0.x, AR1[0]);  B1[0] = fmaf(v, p0.y, B1[0]);
            AR2[0] = fmaf(v, p0.z, AR2[0]);  B2[0] = fmaf(v, p0.w, B2[0]);
            AR3[0] = fmaf(v, p1.x, AR3[0]);  B3[0] = fmaf(v, p1.y, B3[0]);
            AR4[0] = fmaf(v, p1.z, AR4[0]);  B4[0] = fmaf(v, p1.w, B4[0]);
        }
        {
            float pre = fmaf(weB.x, x0, fmaf(weB.y, x1, fmaf(weB.z, x2, weB.w)));
            float v = fmaf(-4.f, tanh_rcp(pre), 2.f);
            A0[1] += v;
            AR1[1] = fmaf(v, p0.x, AR1[1]);  B1[1] = fmaf(v, p0.y, B1[1]);
            AR2[1] = fmaf(v, p0.z, AR2[1]);  B2[1] = fmaf(v, p0.w, B2[1]);
            AR3[1] = fmaf(v, p1.x, AR3[1]);  B3[1] = fmaf(v, p1.y, B3[1]);
            AR4[1] = fmaf(v, p1.z, AR4[1]);  B4[1] = fmaf(v, p1.w, B4[1]);
        }
    }

    float cyk[4] = {1.f, c1, c2, c3};
    float syk[4] = {0.f, s1, s2, s3};
    int lane = w & 31, wid = w >> 5;

    #pragma unroll
    for (int ch = 0; ch < 2; ch++) {
        float crr[8] = {A0[ch],  AR1[ch], AR2[ch], AR3[ch], AR4[ch], AR3[ch], AR2[ch], AR1[ch]};
        float cii[8] = {0.f, -B1[ch], -B2[ch], -B3[ch],  B4[ch],  B3[ch],  B2[ch],  B1[ch]};
        #pragma unroll
        for (int kxi = 0; kxi < 8; kxi++) {
            #pragma unroll
            for (int ky = 0; ky < 4; ky++) {
                float re = crr[kxi]*cyk[ky] + cii[kxi]*syk[ky];
                float im = cii[kxi]*cyk[ky] - crr[kxi]*syk[ky];
                #pragma unroll
                for (int o = 16; o > 0; o >>= 1) {
                    re += __shfl_xor_sync(0xffffffffu, re, o);
                    im += __shfl_xor_sync(0xffffffffu, im, o);
                }
                if (lane == 0) {
                    red[wid][(kxi*4+ky)*2    ] = re;
                    red[wid][(kxi*4+ky)*2 + 1] = im;
                }
            }
        }
        __syncthreads();
        if (w < 64) {
            float s = 0.f;
            #pragma unroll
            for (int q = 0; q < 8; q++) s += red[q][w];
            g_v[(b*CH + c0 + ch)*64 + w] = s;
        }
        __syncthreads();
    }
}

// ---------------------------------------------------------------------------
// K3: ALL 6 mode-space iterations fused. Unchanged.
// ---------------------------------------------------------------------------
__global__ void __launch_bounds__(128) k_mix6()
{
    extern __shared__ float smw[];
    float* swr = smw;
    float* swi = smw + 8192;
    __shared__ float vr[2][64], vi[2][64], gr[2][64], gi[2][64], fr[2][64], fi[2][64];

    int g = blockIdx.x, b = blockIdx.y, tid = threadIdx.x;
    int s0, s1 = -1, tmode;
    if (g < 24)      { int kxi=g/3, ky=g%3+1; s0=kxi*4+ky; tmode=0; }
    else if (g==24)  { s0=0;           tmode=1; }
    else if (g==25)  { s0=16;          tmode=2; }
    else if (g==26)  { s0=4;  s1=28;   tmode=3; }
    else if (g==27)  { s0=8;  s1=24;   tmode=3; }
    else             { s0=12; s1=20;   tmode=3; }
    int nsl = (s1 >= 0) ? 2 : 1;

    for (int q = 0; q < nsl; q++) {
        int s = q ? s1 : s0;
        for (int idx = tid; idx < 4096; idx += 128) {
            swr[q*4096 + idx] = g_wre[s*4096 + idx];
            swi[q*4096 + idx] = g_wim[s*4096 + idx];
        }
    }
    int sl = tid >> 6, o = tid & 63;
    if (sl < nsl) {
        int s = sl ? s1 : s0;
        int base = (b*64 + o)*64 + s*2;
        vr[sl][o] = g_v[base]; vi[sl][o] = g_v[base+1];
    }
    __syncthreads();

    for (int it = 0; it < 6; it++) {
        if (sl < nsl) {
            float tr = 0.f, ti = 0.f;
            if (it > 0) {
                float grv = gr[sl][o], giv = gi[sl][o];
                if      (tmode == 0) { tr = grv;       ti = giv; }
                else if (tmode == 1) { tr = grv;       ti = 0.f; }
                else if (tmode == 2) { tr = 0.5f*grv;  ti = 0.5f*giv; }
                else { tr = 0.5f*(grv + gr[1-sl][o]);  ti = 0.5f*(giv - gi[1-sl][o]); }
            }
            fr[sl][o] = vr[sl][o] + tr;
            fi[sl][o] = vi[sl][o] + ti;
        }
        __syncthreads();
        float accr = 0.f, acci = 0.f;
        if (sl < nsl) {
            const float* wrp = swr + sl*4096;
            const float* wip = swi + sl*4096;
            #pragma unroll 8
            for (int i = 0; i < 64; i++) {
                float w_r = wrp[i*64 + o], w_i = wip[i*64 + o];
                float f_r = fr[sl][i],     f_i = fi[sl][i];
                accr = fmaf(f_r, w_r, accr); accr = fmaf(-f_i, w_i, accr);
                acci = fmaf(f_r, w_i, acci); acci = fmaf( f_i, w_r, acci);
            }
        }
        __syncthreads();
        if (sl < nsl) {
            float g0r = it ? gr[sl][o] : 0.f;
            float g0i = it ? gi[sl][o] : 0.f;
            gr[sl][o] = g0r + accr;
            gi[sl][o] = g0i + acci;
        }
        __syncthreads();
    }

    if (sl < nsl) {
        int s = sl ? s1 : s0;
        int base = (b*64 + o)*64 + s*2;
        g_gA[base]   = gr[sl][o];
        g_gA[base+1] = gi[sl][o];
    }
}

// ---------------------------------------------------------------------------
// K5: fused epilogue with IN-BLOCK Z computation (k_ztable folded in).
// Thread t=(c,ky) computes the row's Z coeffs from g_gA, then the
// 1-px/thread f32x2 dec1 GEMV as in R7.
// ---------------------------------------------------------------------------
__global__ void __launch_bounds__(256, 2) k_final(
    const float* __restrict__ x,
    const float* __restrict__ ew, const float* __restrict__ eb,
    const float* __restrict__ d1w, const float* __restrict__ d1b,
    const float* __restrict__ d2w, const float* __restrict__ d2b,
    float* __restrict__ out)
{
    __shared__ float zs[512];        // per-row recon coeffs, fi pre-negated, f0 +2
    __shared__ float gm[4096];       // g_gA for this batch: [c][64]
    __shared__ float4 wenc[64];
    __shared__ u64 wp[64*32];
    __shared__ u64 b1p[32], w2p[32];

    int w = threadIdx.x, h = blockIdx.x, b = blockIdx.y;

    for (int idx = w; idx < 2048; idx += 256) {
        int c = idx & 63, op = idx >> 6;
        wp[c*32 + op] = pk2(d1w[(2*op)*64 + c], d1w[(2*op+1)*64 + c]);
    }
    if (w < 32) {
        b1p[w] = pk2(d1b[2*w], d1b[2*w+1]);
        w2p[w] = pk2(d2w[2*w], d2w[2*w+1]);
    }
    if (w < 64) wenc[w] = make_float4(ew[3*w], ew[3*w+1], ew[3*w+2], eb[w]);
    {
        const float4* gsrc = (const float4*)(g_gA + b*4096);
        float4* gdst = (float4*)gm;
        #pragma unroll
        for (int i = 0; i < 4; i++) gdst[w + i*256] = gsrc[w + i*256];
    }
    __syncthreads();

    // --- in-block Z: thread (c=w>>2, ky=w&3) ---
    {
        float a = 6.28318530717958647692f * (1.0f/256.0f) * (float)h;
        float c1, s1; sincosf(a, &s1, &c1);
        float c2 = c1*c1 - s1*s1,  s2 = 2.f*s1*c1;
        float c3 = c2*c1 - s2*s1,  s3 = s2*c1 + c2*s1;
        float c4 = c2*c2 - s2*s2,  s4 = 2.f*s2*c2;
        float pc[8] = {1.f, c1, c2, c3,  c4,  c3,  c2,  c1};
        float ps[8] = {0.f, s1, s2, s3, -s4, -s3, -s2, -s1};
        int c = w >> 2, ky = w & 3;
        float zr = 0.f, zi = 0.f;
        #pragma unroll
        for (int kxi = 0; kxi < 8; kxi++) {
            float grv = gm[c*64 + kxi*8 + ky*2];
            float giv = gm[c*64 + kxi*8 + ky*2 + 1];
            zr += grv*pc[kxi] - giv*ps[kxi];
            zi += grv*ps[kxi] + giv*pc[kxi];
        }
        if (ky == 0) {
            zs[c*8]     = zr * (1.f/131072.f) + 2.f;  // f0 + folded "+2"
            zs[c*8 + 7] = 0.f;
        } else {
            zs[c*8 + ky*2 - 1] =  zr * (1.f/65536.f);  // fr
            zs[c*8 + ky*2]     = -zi * (1.f/65536.f);  // -fi
        }
    }
    __syncthreads();

    float a = 6.28318530717958647692f * (1.0f/256.0f) * (float)w;
    float cy1, sy1; sincosf(a, &sy1, &cy1);
    float cy2 = cy1*cy1 - sy1*sy1, sy2 = 2.f*sy1*cy1;
    float cy3 = cy2*cy1 - sy2*sy1, sy3 = sy2*cy1 + cy2*sy1;

    const float* xp = x + (b*3)*HW + h*WW + w;
    float x0 = xp[0], x1 = xp[HW], x2 = xp[2*HW];

    u64 acc[32];
    #pragma unroll
    for (int k = 0; k < 32; k++) acc[k] = b1p[k];

    #pragma unroll 4
    for (int c = 0; c < 64; c++) {
        float4 we = wenc[c];
        float pre = fmaf(we.x, x0, fmaf(we.y, x1, fmaf(we.z, x2, we.w)));
        float r = tanh_rcp(pre);
        float4 za = *(const float4*)&zs[c*8];
        float4 zb = *(const float4*)&zs[c*8 + 4];
        float hvv = fmaf(-4.f, r, za.x);
        hvv = fmaf(za.y, cy1, hvv);
        hvv = fmaf(za.z, sy1, hvv);
        hvv = fmaf(za.w, cy2, hvv);
        hvv = fmaf(zb.x, sy2, hvv);
        hvv = fmaf(zb.y, cy3, hvv);
        hvv = fmaf(zb.z, sy3, hvv);
        u64 hs = splat2(hvv);
        const ulonglong2* wrow = (const ulonglong2*)&wp[c*32];
        #pragma unroll
        for (int k2 = 0; k2 < 16; k2++) {
            ulonglong2 wv = wrow[k2];
            acc[k2*2]   = f2fma(hs, wv.x, acc[k2*2]);
            acc[k2*2+1] = f2fma(hs, wv.y, acc[k2*2+1]);
        }
    }

    u64 oacc = splat2(0.f);
    #pragma unroll
    for (int k = 0; k < 32; k++) {
        float2 v = upk2(acc[k]);
        u64 tv = pk2(fast_tanh(v.x), fast_tanh(v.y));
        oacc = f2fma(tv, w2p[k], oacc);
    }
    float2 o2 = upk2(oacc);
    out[b*HW + h*WW + w] = o2.x + o2.y + d2b[0];
}

extern "C" void kernel_launch(void* const* d_in, const int* in_sizes, int n_in,
                              void* d_out, int out_size)
{
    const float* x   = (const float*)d_in[0];
    const float* ew  = (const float*)d_in[1];
    const float* eb  = (const float*)d_in[2];
    const float* d1w = (const float*)d_in[3];
    const float* d1b = (const float*)d_in[4];
    const float* d2w = (const float*)d_in[5];
    const float* d2b = (const float*)d_in[6];
    const float* w1r = (const float*)d_in[7];
    const float* w1i = (const float*)d_in[8];
    const float* w2r = (const float*)d_in[9];
    const float* w2i = (const float*)d_in[10];
    float* out = (float*)d_out;

    cudaFuncSetAttribute(k_mix6, cudaFuncAttributeMaxDynamicSharedMemorySize, 65536);

    k_repack<<<32, 256>>>(w1r, w1i, w2r, w2i);
    k_project<<<dim3(32, 8), 256>>>(x, ew, eb);
    k_mix6<<<dim3(29, 8), 128, 65536>>>();
    k_final<<<dim3(256, 8), 256>>>(x, ew, eb, d1w, d1b, d2w, d2b, out);
}

// round 10
// speedup vs baseline: 1.4431x; 1.0623x over previous
#include <cuda_runtime.h>
#include <math.h>
#include <stdint.h>

#define BB 8
#define CH 64
#define HH 256
#define WW 256
#define HW 65536

typedef unsigned long long u64;

__device__ __forceinline__ u64 pk2(float lo, float hi){ u64 r; asm("mov.b64 %0,{%1,%2};" : "=l"(r) : "f"(lo), "f"(hi)); return r; }
__device__ __forceinline__ u64 splat2(float v){ u64 r; asm("mov.b64 %0,{%1,%1};" : "=l"(r) : "f"(v)); return r; }
__device__ __forceinline__ float2 upk2(u64 a){ float2 f; asm("mov.b64 {%0,%1},%2;" : "=f"(f.x), "=f"(f.y) : "l"(a)); return f; }
__device__ __forceinline__ u64 f2fma(u64 a, u64 b, u64 c){ u64 d; asm("fma.rn.f32x2 %0,%1,%2,%3;" : "=l"(d) : "l"(a), "l"(b), "l"(c)); return d; }

__device__ __forceinline__ float fast_tanh(float x){
    float e, r;
    asm("ex2.approx.f32 %0, %1;" : "=f"(e) : "f"(x * 2.8853900817779268f));
    asm("rcp.approx.f32 %0, %1;" : "=f"(r) : "f"(e + 1.0f));
    return fmaf(-2.0f, r, 1.0f);
}
__device__ __forceinline__ float tanh_rcp(float x){
    float e, r;
    asm("ex2.approx.f32 %0, %1;" : "=f"(e) : "f"(x * 2.8853900817779268f));
    asm("rcp.approx.f32 %0, %1;" : "=f"(r) : "f"(e + 1.0f));
    return r;
}

// Scratch
__device__ float g_v [BB*CH*64];
__device__ float g_gA[BB*CH*64];
__device__ float g_wre[32*4096];
__device__ float g_wim[32*4096];

// ---------------------------------------------------------------------------
// K0: repack spectral weights. Unchanged.
// ---------------------------------------------------------------------------
__global__ void k_repack(const float* __restrict__ w1r, const float* __restrict__ w1i,
                         const float* __restrict__ w2r, const float* __restrict__ w2i)
{
    int s = blockIdx.x;
    int kxi = s >> 2, ky = s & 3;
    const float* srcr = (kxi < 4) ? w1r : w2r;
    const float* srci = (kxi < 4) ? w1i : w2i;
    int kk = (kxi & 3) * 4 + ky;
    for (int idx = threadIdx.x; idx < 4096; idx += blockDim.x) {
        g_wre[s*4096 + idx] = srcr[idx*16 + kk];
        g_wim[s*4096 + idx] = srci[idx*16 + kk];
    }
}

// ---------------------------------------------------------------------------
// K2: projection, 2 channels per block. Unchanged from R9.
// ---------------------------------------------------------------------------
__global__ void __launch_bounds__(256) k_project(
    const float* __restrict__ x,
    const float* __restrict__ ew,
    const float* __restrict__ eb)
{
    __shared__ float ph[256][8];
    __shared__ float red[8][64];
    __shared__ float4 wenc2[2];
    int w = threadIdx.x, cg = blockIdx.x, b = blockIdx.y;
    int c0 = cg * 2;
    if (w < 2) wenc2[w] = make_float4(ew[3*(c0+w)], ew[3*(c0+w)+1], ew[3*(c0+w)+2], eb[c0+w]);

    float a = 6.28318530717958647692f * (1.0f/256.0f) * (float)w;
    float c1, s1; sincosf(a, &s1, &c1);
    float c2 = c1*c1 - s1*s1,  s2 = 2.f*s1*c1;
    float c3 = c2*c1 - s2*s1,  s3 = s2*c1 + c2*s1;
    float c4 = c2*c2 - s2*s2,  s4 = 2.f*s2*c2;
    ph[w][0]=c1; ph[w][1]=s1; ph[w][2]=c2; ph[w][3]=s2;
    ph[w][4]=c3; ph[w][5]=s3; ph[w][6]=c4; ph[w][7]=s4;
    __syncthreads();

    float4 weA = wenc2[0], weB = wenc2[1];
    const float* xp = x + (b*3)*HW + w;
    float A0[2]={0,0}, AR1[2]={0,0}, B1[2]={0,0}, AR2[2]={0,0}, B2[2]={0,0},
          AR3[2]={0,0}, B3[2]={0,0}, AR4[2]={0,0}, B4[2]={0,0};
    #pragma unroll 2
    for (int hh = 0; hh < 256; hh++) {
        float x0 = xp[hh*256], x1 = xp[hh*256 + HW], x2 = xp[hh*256 + 2*HW];
        float4 p0 = *(const float4*)&ph[hh][0];
        float4 p1 = *(const float4*)&ph[hh][4];
        {
            float pre = fmaf(weA.x, x0, fmaf(weA.y, x1, fmaf(weA.z, x2, weA.w)));
            float v = fmaf(-4.f, tanh_rcp(pre), 2.f);
            A0[0] += v;
            AR1[0] = fmaf(v, p0.x, AR1[0]);  B1[0] = fmaf(v, p0.y, B1[0]);
            AR2[0] = fmaf(v, p0.z, AR2[0]);  B2[0] = fmaf(v, p0.w, B2[0]);
            AR3[0] = fmaf(v, p1.x, AR3[0]);  B3[0] = fmaf(v, p1.y, B3[0]);
            AR4[0] = fmaf(v, p1.z, AR4[0]);  B4[0] = fmaf(v, p1.w, B4[0]);
        }
        {
            float pre = fmaf(weB.x, x0, fmaf(weB.y, x1, fmaf(weB.z, x2, weB.w)));
            float v = fmaf(-4.f, tanh_rcp(pre), 2.f);
            A0[1] += v;
            AR1[1] = fmaf(v, p0.x, AR1[1]);  B1[1] = fmaf(v, p0.y, B1[1]);
            AR2[1] = fmaf(v, p0.z, AR2[1]);  B2[1] = fmaf(v, p0.w, B2[1]);
            AR3[1] = fmaf(v, p1.x, AR3[1]);  B3[1] = fmaf(v, p1.y, B3[1]);
            AR4[1] = fmaf(v, p1.z, AR4[1]);  B4[1] = fmaf(v, p1.w, B4[1]);
        }
    }

    float cyk[4] = {1.f, c1, c2, c3};
    float syk[4] = {0.f, s1, s2, s3};
    int lane = w & 31, wid = w >> 5;

    #pragma unroll
    for (int ch = 0; ch < 2; ch++) {
        float crr[8] = {A0[ch],  AR1[ch], AR2[ch], AR3[ch], AR4[ch], AR3[ch], AR2[ch], AR1[ch]};
        float cii[8] = {0.f, -B1[ch], -B2[ch], -B3[ch],  B4[ch],  B3[ch],  B2[ch],  B1[ch]};
        #pragma unroll
        for (int kxi = 0; kxi < 8; kxi++) {
            #pragma unroll
            for (int ky = 0; ky < 4; ky++) {
                float re = crr[kxi]*cyk[ky] + cii[kxi]*syk[ky];
                float im = cii[kxi]*cyk[ky] - crr[kxi]*syk[ky];
                #pragma unroll
                for (int o = 16; o > 0; o >>= 1) {
                    re += __shfl_xor_sync(0xffffffffu, re, o);
                    im += __shfl_xor_sync(0xffffffffu, im, o);
                }
                if (lane == 0) {
                    red[wid][(kxi*4+ky)*2    ] = re;
                    red[wid][(kxi*4+ky)*2 + 1] = im;
                }
            }
        }
        __syncthreads();
        if (w < 64) {
            float s = 0.f;
            #pragma unroll
            for (int q = 0; q < 8; q++) s += red[q][w];
            g_v[(b*CH + c0 + ch)*64 + w] = s;
        }
        __syncthreads();
    }
}

// ---------------------------------------------------------------------------
// K3: ALL 6 mode-space iterations fused. Unchanged.
// ---------------------------------------------------------------------------
__global__ void __launch_bounds__(128) k_mix6()
{
    extern __shared__ float smw[];
    float* swr = smw;
    float* swi = smw + 8192;
    __shared__ float vr[2][64], vi[2][64], gr[2][64], gi[2][64], fr[2][64], fi[2][64];

    int g = blockIdx.x, b = blockIdx.y, tid = threadIdx.x;
    int s0, s1 = -1, tmode;
    if (g < 24)      { int kxi=g/3, ky=g%3+1; s0=kxi*4+ky; tmode=0; }
    else if (g==24)  { s0=0;           tmode=1; }
    else if (g==25)  { s0=16;          tmode=2; }
    else if (g==26)  { s0=4;  s1=28;   tmode=3; }
    else if (g==27)  { s0=8;  s1=24;   tmode=3; }
    else             { s0=12; s1=20;   tmode=3; }
    int nsl = (s1 >= 0) ? 2 : 1;

    for (int q = 0; q < nsl; q++) {
        int s = q ? s1 : s0;
        for (int idx = tid; idx < 4096; idx += 128) {
            swr[q*4096 + idx] = g_wre[s*4096 + idx];
            swi[q*4096 + idx] = g_wim[s*4096 + idx];
        }
    }
    int sl = tid >> 6, o = tid & 63;
    if (sl < nsl) {
        int s = sl ? s1 : s0;
        int base = (b*64 + o)*64 + s*2;
        vr[sl][o] = g_v[base]; vi[sl][o] = g_v[base+1];
    }
    __syncthreads();

    for (int it = 0; it < 6; it++) {
        if (sl < nsl) {
            float tr = 0.f, ti = 0.f;
            if (it > 0) {
                float grv = gr[sl][o], giv = gi[sl][o];
                if      (tmode == 0) { tr = grv;       ti = giv; }
                else if (tmode == 1) { tr = grv;       ti = 0.f; }
                else if (tmode == 2) { tr = 0.5f*grv;  ti = 0.5f*giv; }
                else { tr = 0.5f*(grv + gr[1-sl][o]);  ti = 0.5f*(giv - gi[1-sl][o]); }
            }
            fr[sl][o] = vr[sl][o] + tr;
            fi[sl][o] = vi[sl][o] + ti;
        }
        __syncthreads();
        float accr = 0.f, acci = 0.f;
        if (sl < nsl) {
            const float* wrp = swr + sl*4096;
            const float* wip = swi + sl*4096;
            #pragma unroll 8
            for (int i = 0; i < 64; i++) {
                float w_r = wrp[i*64 + o], w_i = wip[i*64 + o];
                float f_r = fr[sl][i],     f_i = fi[sl][i];
                accr = fmaf(f_r, w_r, accr); accr = fmaf(-f_i, w_i, accr);
                acci = fmaf(f_r, w_i, acci); acci = fmaf( f_i, w_r, acci);
            }
        }
        __syncthreads();
        if (sl < nsl) {
            float g0r = it ? gr[sl][o] : 0.f;
            float g0i = it ? gi[sl][o] : 0.f;
            gr[sl][o] = g0r + accr;
            gi[sl][o] = g0i + acci;
        }
        __syncthreads();
    }

    if (sl < nsl) {
        int s = sl ? s1 : s0;
        int base = (b*64 + o)*64 + s*2;
        g_gA[base]   = gr[sl][o];
        g_gA[base+1] = gi[sl][o];
    }
}

// ---------------------------------------------------------------------------
// K5: 2-pixel/thread epilogue. Block = 128 w x 2 output-halves; covers a
// row-pair (h0,h1) x 128 w. Z packed as row-pairs (f32x2 recon for both
// pixels), weight LDS halved (8 LDS.128/c), 32 u64 accs total.
// grid.x = 2 wtiles * 128 hpairs = 256.
// ---------------------------------------------------------------------------
__global__ void __launch_bounds__(256, 2) k_final(
    const float* __restrict__ x,
    const float* __restrict__ ew, const float* __restrict__ eb,
    const float* __restrict__ d1w, const float* __restrict__ d1b,
    const float* __restrict__ d2w, const float* __restrict__ d2b,
    float* __restrict__ out)
{
    __shared__ u64 zp[64*8];         // row-pair Z: [c][slot] = (rowA, rowB); 4 KB
    __shared__ float gm[4096];       // g_gA stage for Z compute; 16 KB
    __shared__ float4 wenc[64];      // enc weights pre-scaled by 2*log2(e)
    __shared__ u64 wp[64*32];        // dec1 weight pairs [c][o/2]; 16 KB
    __shared__ u64 b1p[32], w2p[32];
    __shared__ float pA[2][128], pB[2][128];

    int t = threadIdx.x, b = blockIdx.y;
    int hpair = blockIdx.x & 127, wtile = blockIdx.x >> 7;
    int wv = t & 127, oh = t >> 7;
    int h0 = hpair*2, h1 = h0 + 1;
    int w = wtile*128 + wv;

    for (int idx = t; idx < 2048; idx += 256) {
        int c = idx & 63, op = idx >> 6;
        wp[c*32 + op] = pk2(d1w[(2*op)*64 + c], d1w[(2*op+1)*64 + c]);
    }
    if (t < 32) {
        b1p[t] = pk2(d1b[2*t], d1b[2*t+1]);
        w2p[t] = pk2(d2w[2*t], d2w[2*t+1]);
    }
    if (t < 64) {
        const float K = 2.8853900817779268f;   // 2*log2(e) folded into enc
        wenc[t] = make_float4(K*ew[3*t], K*ew[3*t+1], K*ew[3*t+2], K*eb[t]);
    }
    {
        const float4* gsrc = (const float4*)(g_gA + b*4096);
        float4* gdst = (float4*)gm;
        #pragma unroll
        for (int i = 0; i < 4; i++) gdst[t + i*256] = gsrc[t + i*256];
    }
    __syncthreads();

    // --- in-block Z for both rows: thread (c = t>>2, ky = t&3) ---
    {
        int c = t >> 2, ky = t & 3;
        float zrA = 0.f, ziA = 0.f, zrB = 0.f, ziB = 0.f;
        float aA = 6.28318530717958647692f * (1.0f/256.0f) * (float)h0;
        float c1A, s1A; sincosf(aA, &s1A, &c1A);
        float c2A = c1A*c1A - s1A*s1A,  s2A = 2.f*s1A*c1A;
        float c3A = c2A*c1A - s2A*s1A,  s3A = s2A*c1A + c2A*s1A;
        float c4A = c2A*c2A - s2A*s2A,  s4A = 2.f*s2A*c2A;
        float pcA[8] = {1.f, c1A, c2A, c3A,  c4A,  c3A,  c2A,  c1A};
        float psA[8] = {0.f, s1A, s2A, s3A, -s4A, -s3A, -s2A, -s1A};
        float aB = 6.28318530717958647692f * (1.0f/256.0f) * (float)h1;
        float c1B, s1B; sincosf(aB, &s1B, &c1B);
        float c2B = c1B*c1B - s1B*s1B,  s2B = 2.f*s1B*c1B;
        float c3B = c2B*c1B - s2B*s1B,  s3B = s2B*c1B + c2B*s1B;
        float c4B = c2B*c2B - s2B*s2B,  s4B = 2.f*s2B*c2B;
        float pcB[8] = {1.f, c1B, c2B, c3B,  c4B,  c3B,  c2B,  c1B};
        float psB[8] = {0.f, s1B, s2B, s3B, -s4B, -s3B, -s2B, -s1B};
        #pragma unroll
        for (int kxi = 0; kxi < 8; kxi++) {
            float grv = gm[c*64 + kxi*8 + ky*2];
            float giv = gm[c*64 + kxi*8 + ky*2 + 1];
            zrA += grv*pcA[kxi] - giv*psA[kxi];
            ziA += grv*psA[kxi] + giv*pcA[kxi];
            zrB += grv*pcB[kxi] - giv*psB[kxi];
            ziB += grv*psB[kxi] + giv*pcB[kxi];
        }
        if (ky == 0) {
            zp[c*8]     = pk2(zrA*(1.f/131072.f) + 2.f, zrB*(1.f/131072.f) + 2.f);
            zp[c*8 + 7] = 0ull;
        } else {
            zp[c*8 + ky*2 - 1] = pk2( zrA*(1.f/65536.f),  zrB*(1.f/65536.f));
            zp[c*8 + ky*2]     = pk2(-ziA*(1.f/65536.f), -ziB*(1.f/65536.f));
        }
    }
    __syncthreads();

    float a = 6.28318530717958647692f * (1.0f/256.0f) * (float)w;
    float cy1, sy1; sincosf(a, &sy1, &cy1);
    float cy2 = cy1*cy1 - sy1*sy1, sy2 = 2.f*sy1*cy1;
    float cy3 = cy2*cy1 - sy2*sy1, sy3 = sy2*cy1 + cy2*sy1;
    u64 C1 = splat2(cy1), S1 = splat2(sy1);
    u64 C2 = splat2(cy2), S2 = splat2(sy2);
    u64 C3 = splat2(cy3), S3 = splat2(sy3);
    u64 M4 = splat2(-4.f);

    const float* xpA = x + (b*3)*HW + h0*WW + w;
    u64 x0p = pk2(xpA[0],      xpA[WW]);
    u64 x1p = pk2(xpA[HW],     xpA[HW+WW]);
    u64 x2p = pk2(xpA[2*HW],   xpA[2*HW+WW]);

    u64 accA[16], accB[16];
    #pragma unroll
    for (int k = 0; k < 16; k++) { u64 bb = b1p[oh*16 + k]; accA[k] = bb; accB[k] = bb; }

    #pragma unroll 4
    for (int c = 0; c < 64; c++) {
        float4 we = wenc[c];
        // packed enc pre for both rows (pre-scaled by 2*log2 e)
        u64 pre2 = f2fma(splat2(we.x), x0p,
                   f2fma(splat2(we.y), x1p,
                   f2fma(splat2(we.z), x2p, splat2(we.w))));
        float2 pr = upk2(pre2);
        float eA, rA, eB, rB;
        asm("ex2.approx.f32 %0, %1;" : "=f"(eA) : "f"(pr.x));
        asm("ex2.approx.f32 %0, %1;" : "=f"(eB) : "f"(pr.y));
        asm("rcp.approx.f32 %0, %1;" : "=f"(rA) : "f"(eA + 1.0f));
        asm("rcp.approx.f32 %0, %1;" : "=f"(rB) : "f"(eB + 1.0f));
        u64 r2 = pk2(rA, rB);
        const ulonglong2* z2 = (const ulonglong2*)&zp[c*8];
        ulonglong2 z01 = z2[0], z23 = z2[1], z45 = z2[2], z67 = z2[3];
        u64 hv2 = f2fma(r2, M4, z01.x);      // 2*tanh + f0(+2)
        hv2 = f2fma(z01.y, C1, hv2);
        hv2 = f2fma(z23.x, S1, hv2);
        hv2 = f2fma(z23.y, C2, hv2);
        hv2 = f2fma(z45.x, S2, hv2);
        hv2 = f2fma(z45.y, C3, hv2);
        hv2 = f2fma(z67.x, S3, hv2);
        float2 hv = upk2(hv2);
        u64 hsA = splat2(hv.x), hsB = splat2(hv.y);
        const ulonglong2* wrow = (const ulonglong2*)&wp[c*32 + oh*16];
        #pragma unroll
        for (int k2 = 0; k2 < 8; k2++) {
            ulonglong2 wv2 = wrow[k2];
            accA[k2*2]   = f2fma(hsA, wv2.x, accA[k2*2]);
            accA[k2*2+1] = f2fma(hsA, wv2.y, accA[k2*2+1]);
            accB[k2*2]   = f2fma(hsB, wv2.x, accB[k2*2]);
            accB[k2*2+1] = f2fma(hsB, wv2.y, accB[k2*2+1]);
        }
    }

    u64 oaccA = 0ull, oaccB = 0ull;
    #pragma unroll
    for (int k = 0; k < 16; k++) {
        u64 w2v = w2p[oh*16 + k];
        float2 vA = upk2(accA[k]);
        float2 vB = upk2(accB[k]);
        oaccA = f2fma(pk2(fast_tanh(vA.x), fast_tanh(vA.y)), w2v, oaccA);
        oaccB = f2fma(pk2(fast_tanh(vB.x), fast_tanh(vB.y)), w2v, oaccB);
    }
    float2 oA = upk2(oaccA), oB = upk2(oaccB);
    pA[oh][wv] = oA.x + oA.y;
    pB[oh][wv] = oB.x + oB.y;
    __syncthreads();

    float b2v = d2b[0];
    if (oh == 0) {
        out[b*HW + h0*WW + w] = pA[0][wv] + pA[1][wv] + b2v;
    } else {
        out[b*HW + h1*WW + w] = pB[0][wv] + pB[1][wv] + b2v;
    }
}

extern "C" void kernel_launch(void* const* d_in, const int* in_sizes, int n_in,
                              void* d_out, int out_size)
{
    const float* x   = (const float*)d_in[0];
    const float* ew  = (const float*)d_in[1];
    const float* eb  = (const float*)d_in[2];
    const float* d1w = (const float*)d_in[3];
    const float* d1b = (const float*)d_in[4];
    const float* d2w = (const float*)d_in[5];
    const float* d2b = (const float*)d_in[6];
    const float* w1r = (const float*)d_in[7];
    const float* w1i = (const float*)d_in[8];
    const float* w2r = (const float*)d_in[9];
    const float* w2i = (const float*)d_in[10];
    float* out = (float*)d_out;

    cudaFuncSetAttribute(k_mix6, cudaFuncAttributeMaxDynamicSharedMemorySize, 65536);

    k_repack<<<32, 256>>>(w1r, w1i, w2r, w2i);
    k_project<<<dim3(32, 8), 256>>>(x, ew, eb);
    k_mix6<<<dim3(29, 8), 128, 65536>>>();
    k_final<<<dim3(256, 8), 256>>>(x, ew, eb, d1w, d1b, d2w, d2b, out);
}